// round 8
// baseline (speedup 1.0000x reference)
#include <cuda_runtime.h>
#include <cstdint>

#define NB 16
#define NN 8192
#define NDIM 384
#define NR 64
#define NG 128
#define NS 64
#define MT (NB*NN)   // 131072 rows

// ---------------- scratch (no allocations allowed) ----------------
__device__ __align__(256) float g_h[(size_t)MT*NR];   // 33.5 MB
__device__ __align__(256) float g_y[(size_t)MT*NR];   // 33.5 MB
__device__ __align__(256) int   g_idx[2*MT];          // normalized int32 indices
__device__ int g_is64;

__device__ __forceinline__ float silu_f(float x){ return x / (1.0f + __expf(-x)); }

__device__ __forceinline__ void fma4x4(float (&acc)[4][4], float4 a, float4 b){
    float av[4] = {a.x,a.y,a.z,a.w};
    float bv[4] = {b.x,b.y,b.z,b.w};
    #pragma unroll
    for (int i=0;i<4;i++)
        #pragma unroll
        for (int j=0;j<4;j++)
            acc[i][j] += av[i]*bv[j];
}

// ---------------- idx dtype probe + normalize ----------------
// Values are in [0, 8192). If the array is int64 (little-endian), every odd
// 32-bit word is 0. If int32, odd words are random nonzero indices
// (P[all 128 zero] ~ (1/8192)^128 ~ 0).
__global__ void probe_idx_kernel(const unsigned int* __restrict__ w){
    __shared__ int ok;
    if (threadIdx.x == 0) ok = 1;
    __syncthreads();
    if (w[2*threadIdx.x + 1] != 0u) ok = 0;   // benign race, all write 0
    __syncthreads();
    if (threadIdx.x == 0) g_is64 = ok;
}

__global__ void convert_idx_kernel(const void* __restrict__ p){
    int i = blockIdx.x*blockDim.x + threadIdx.x;
    if (i >= 2*MT) return;
    if (g_is64) g_idx[i] = (int)((const long long*)p)[i];
    else        g_idx[i] = ((const int*)p)[i];
}

// ---------------- K1: h = silu(X @ Wd^T + bd) ----------------
// C[131072,64] = A[131072,384] * Wd[64,384]^T. BM=64, BN=64, BK=32.
__global__ __launch_bounds__(256) void down_kernel(
    const float* __restrict__ A, const float* __restrict__ Wd,
    const float* __restrict__ bd)
{
    __shared__ float As[32][68];  // k-major: As[k][m]
    __shared__ float Bs[32][68];  // k-major: Bs[k][n] = Wd[n][k]
    const int tid = threadIdx.x;
    const int tx = tid & 15, ty = tid >> 4;
    const int m0 = blockIdx.x * 64;
    const int lr = tid >> 3;         // 0..31
    const int lk = (tid & 7) * 4;    // 0..28

    float acc[4][4] = {};
    for (int kk = 0; kk < NDIM; kk += 32){
        float4 a0 = *(const float4*)(A + (size_t)(m0+lr   )*NDIM + kk + lk);
        float4 a1 = *(const float4*)(A + (size_t)(m0+lr+32)*NDIM + kk + lk);
        float4 b0 = *(const float4*)(Wd + (size_t)(lr   )*NDIM + kk + lk);
        float4 b1 = *(const float4*)(Wd + (size_t)(lr+32)*NDIM + kk + lk);
        __syncthreads();
        As[lk+0][lr]=a0.x; As[lk+1][lr]=a0.y; As[lk+2][lr]=a0.z; As[lk+3][lr]=a0.w;
        As[lk+0][lr+32]=a1.x; As[lk+1][lr+32]=a1.y; As[lk+2][lr+32]=a1.z; As[lk+3][lr+32]=a1.w;
        Bs[lk+0][lr]=b0.x; Bs[lk+1][lr]=b0.y; Bs[lk+2][lr]=b0.z; Bs[lk+3][lr]=b0.w;
        Bs[lk+0][lr+32]=b1.x; Bs[lk+1][lr+32]=b1.y; Bs[lk+2][lr+32]=b1.z; Bs[lk+3][lr+32]=b1.w;
        __syncthreads();
        #pragma unroll
        for (int k = 0; k < 32; k++){
            float4 af = *(const float4*)&As[k][ty*4];
            float4 bf = *(const float4*)&Bs[k][tx*4];
            fma4x4(acc, af, bf);
        }
    }
    float4 bb = *(const float4*)(bd + tx*4);
    #pragma unroll
    for (int i=0;i<4;i++){
        float4 o;
        o.x = silu_f(acc[i][0] + bb.x);
        o.y = silu_f(acc[i][1] + bb.y);
        o.z = silu_f(acc[i][2] + bb.z);
        o.w = silu_f(acc[i][3] + bb.w);
        *(float4*)(g_h + (size_t)(m0+ty*4+i)*NR + tx*4) = o;
    }
}

// ---------------- K2: fused per-(b,g) branch (branch 1 only; branch 0 is dead)
//   X[t][r]  = h[b, idx0[b, g*64+t], r]          (gather fused into load)
//   F        = U^T @ X
//   F2       = F + silu(LN(F) @ Wa^T + ba)
//   Y        = U @ F2  -> g_y
#define K3_SMEM (5*64*68*4 + 3*64*4)
__global__ __launch_bounds__(256) void group_kernel(
    const float* __restrict__ subU, const float* __restrict__ Wa,
    const float* __restrict__ ba, const float* __restrict__ gamma,
    const float* __restrict__ beta)
{
    extern __shared__ float sm[];
    float* Ug  = sm;              // [64][68]  Ug[t][s]  = U[t][s] (as stored)
    float* Ut  = Ug  + 64*68;     // [64][68]  Ut[t][s]  = U[s][t] (transposed)
    float* Xs  = Ut  + 64*68;     // [64][68]  sub_x[t][r]; later LNT[k][s]
    float* Fs  = Xs  + 64*68;     // [64][68]  F[s][r]; later F2
    float* WaT = Fs  + 64*68;     // [64][68]  WaT[k][r] = Wa[r][k]
    float* sGa = WaT + 64*68;     // [64]
    float* sBe = sGa + 64;        // [64]
    float* sBa = sBe + 64;        // [64]

    const int tid = threadIdx.x;
    const int tx = tid & 15, ty = tid >> 4;
    const int bg = blockIdx.x;
    const int b = bg >> 7, g = bg & 127;
    const float* U = subU + ((size_t)(16 + b)*128 + g)*4096;  // sub_U[1][b][g]

    const int row = tid >> 2;        // 0..63
    const int c0  = (tid & 3) * 16;  // 0,16,32,48
    const int src = g_idx[b*NN + g*64 + row];                 // idx[0]
    const float* hsrc = g_h + ((size_t)b*NN + src)*NR;

    #pragma unroll
    for (int c = 0; c < 16; c += 4){
        float4 u = *(const float4*)(U + row*64 + c0 + c);
        *(float4*)&Ug[row*68 + c0 + c] = u;
        Ut[(c0+c+0)*68 + row] = u.x;
        Ut[(c0+c+1)*68 + row] = u.y;
        Ut[(c0+c+2)*68 + row] = u.z;
        Ut[(c0+c+3)*68 + row] = u.w;
        float4 w = *(const float4*)(Wa + row*64 + c0 + c);
        WaT[(c0+c+0)*68 + row] = w.x;
        WaT[(c0+c+1)*68 + row] = w.y;
        WaT[(c0+c+2)*68 + row] = w.z;
        WaT[(c0+c+3)*68 + row] = w.w;
        float4 x = *(const float4*)(hsrc + c0 + c);
        *(float4*)&Xs[row*68 + c0 + c] = x;
    }
    if (tid < 64){ sGa[tid]=gamma[tid]; sBe[tid]=beta[tid]; sBa[tid]=ba[tid]; }
    __syncthreads();

    // GEMM1: F[s][r] = sum_t U[t][s] * X[t][r]
    float accF[4][4] = {};
    #pragma unroll 8
    for (int t = 0; t < 64; t++){
        float4 af = *(const float4*)&Ug[t*68 + ty*4];
        float4 bf = *(const float4*)&Xs[t*68 + tx*4];
        fma4x4(accF, af, bf);
    }
    #pragma unroll
    for (int i=0;i<4;i++)
        *(float4*)&Fs[(ty*4+i)*68 + tx*4] =
            make_float4(accF[i][0],accF[i][1],accF[i][2],accF[i][3]);
    __syncthreads();

    // LayerNorm over r (64) for row s=row; ddof=0, eps=1e-5
    float ssum=0.f, ssq=0.f;
    #pragma unroll
    for (int c=0;c<16;c+=4){
        float4 f = *(const float4*)&Fs[row*68 + c0 + c];
        ssum += f.x+f.y+f.z+f.w;
        ssq  += f.x*f.x + f.y*f.y + f.z*f.z + f.w*f.w;
    }
    ssum += __shfl_xor_sync(0xffffffffu, ssum, 1);
    ssq  += __shfl_xor_sync(0xffffffffu, ssq , 1);
    ssum += __shfl_xor_sync(0xffffffffu, ssum, 2);
    ssq  += __shfl_xor_sync(0xffffffffu, ssq , 2);
    float mean = ssum * (1.0f/64.0f);
    float var  = ssq  * (1.0f/64.0f) - mean*mean;
    float rstd = rsqrtf(var + 1e-5f);
    // LNT[k][s] into Xs (transposed for GEMM2 A-side LDS.128)
    #pragma unroll
    for (int c=0;c<16;c+=4){
        float4 f = *(const float4*)&Fs[row*68 + c0 + c];
        Xs[(c0+c+0)*68 + row] = (f.x-mean)*rstd*sGa[c0+c+0] + sBe[c0+c+0];
        Xs[(c0+c+1)*68 + row] = (f.y-mean)*rstd*sGa[c0+c+1] + sBe[c0+c+1];
        Xs[(c0+c+2)*68 + row] = (f.z-mean)*rstd*sGa[c0+c+2] + sBe[c0+c+2];
        Xs[(c0+c+3)*68 + row] = (f.w-mean)*rstd*sGa[c0+c+3] + sBe[c0+c+3];
    }
    __syncthreads();

    // GEMM2: G[s][r] = sum_k LN(F)[s][k] * Wa[r][k];  F2 = F + silu(G + ba)
    float accG[4][4] = {};
    #pragma unroll 8
    for (int t = 0; t < 64; t++){
        float4 af = *(const float4*)&Xs[t*68 + ty*4];
        float4 bf = *(const float4*)&WaT[t*68 + tx*4];
        fma4x4(accG, af, bf);
    }
    #pragma unroll
    for (int i=0;i<4;i++){
        float4 o;
        o.x = accF[i][0] + silu_f(accG[i][0] + sBa[tx*4+0]);
        o.y = accF[i][1] + silu_f(accG[i][1] + sBa[tx*4+1]);
        o.z = accF[i][2] + silu_f(accG[i][2] + sBa[tx*4+2]);
        o.w = accF[i][3] + silu_f(accG[i][3] + sBa[tx*4+3]);
        *(float4*)&Fs[(ty*4+i)*68 + tx*4] = o;
    }
    __syncthreads();

    // GEMM3: Y[s][r] = sum_t U[s][t] * F2[t][r]
    float accY[4][4] = {};
    #pragma unroll 8
    for (int t = 0; t < 64; t++){
        float4 af = *(const float4*)&Ut[t*68 + ty*4];
        float4 bf = *(const float4*)&Fs[t*68 + tx*4];
        fma4x4(accY, af, bf);
    }
    float* yout = g_y + ((size_t)b*NN + g*64)*NR;
    #pragma unroll
    for (int i=0;i<4;i++)
        *(float4*)(yout + (size_t)(ty*4+i)*NR + tx*4) =
            make_float4(accY[i][0],accY[i][1],accY[i][2],accY[i][3]);
}

// ---------------- K3: h <- h + y + gather(y, idx[1])  (in-place, per-element RMW)
__global__ void combine_kernel(){
    int gid = blockIdx.x*blockDim.x + threadIdx.x;   // one float4 each
    if (gid >= MT*NR/4) return;
    int rowi = gid >> 4;          // row 0..131071
    int q    = (gid & 15) * 4;    // col offset
    int b = rowi >> 13, j = rowi & (NN-1);
    int src = g_idx[MT + b*NN + j];                   // idx[1]
    float4 yg = *(const float4*)(g_y + ((size_t)b*NN + src)*NR + q);
    float4 yd = *(const float4*)(g_y + (size_t)rowi*NR + q);
    float4 hh = *(const float4*)(g_h + (size_t)rowi*NR + q);
    hh.x += yg.x + yd.x;  hh.y += yg.y + yd.y;
    hh.z += yg.z + yd.z;  hh.w += yg.w + yd.w;
    *(float4*)(g_h + (size_t)rowi*NR + q) = hh;
}

// ---------------- K4: out = h @ Wu^T + bu ----------------
// out[131072,384] = h[131072,64] * Wu[384,64]^T. BM=64, BN=128, single K pass.
#define K4_SMEM (64*68*4 + 64*132*4 + 128*4)
__global__ __launch_bounds__(256) void up_kernel(
    const float* __restrict__ Wu, const float* __restrict__ bu,
    float* __restrict__ out)
{
    extern __shared__ float sm[];
    float* Hs  = sm;            // [64][68]   Hs[k][m]
    float* Ws  = Hs + 64*68;    // [64][132]  Ws[k][n] = Wu[n0+n][k]
    float* sBu = Ws + 64*132;   // [128]
    const int tid = threadIdx.x;
    const int tx = tid & 15, ty = tid >> 4;
    const int m0 = blockIdx.x * 64;
    const int n0 = blockIdx.y * 128;
    {
        int row = tid >> 2, c0 = (tid & 3)*16;
        const float* src = g_h + (size_t)(m0+row)*NR;
        #pragma unroll
        for (int c=0;c<16;c+=4){
            float4 v = *(const float4*)(src + c0 + c);
            Hs[(c0+c+0)*68 + row] = v.x;
            Hs[(c0+c+1)*68 + row] = v.y;
            Hs[(c0+c+2)*68 + row] = v.z;
            Hs[(c0+c+3)*68 + row] = v.w;
        }
        int nloc = tid >> 1, half = (tid & 1)*32;
        const float* wsrc = Wu + (size_t)(n0+nloc)*NR + half;
        #pragma unroll
        for (int c=0;c<32;c+=4){
            float4 w = *(const float4*)(wsrc + c);
            Ws[(half+c+0)*132 + nloc] = w.x;
            Ws[(half+c+1)*132 + nloc] = w.y;
            Ws[(half+c+2)*132 + nloc] = w.z;
            Ws[(half+c+3)*132 + nloc] = w.w;
        }
        if (tid < 128) sBu[tid] = bu[n0 + tid];
    }
    __syncthreads();

    float acc[4][8] = {};
    #pragma unroll 8
    for (int k=0;k<64;k++){
        float4 af = *(const float4*)&Hs[k*68 + ty*4];
        float4 b0 = *(const float4*)&Ws[k*132 + tx*8];
        float4 b1 = *(const float4*)&Ws[k*132 + tx*8 + 4];
        float av[4]={af.x,af.y,af.z,af.w};
        float bv[8]={b0.x,b0.y,b0.z,b0.w,b1.x,b1.y,b1.z,b1.w};
        #pragma unroll
        for (int i=0;i<4;i++)
            #pragma unroll
            for (int j=0;j<8;j++)
                acc[i][j] += av[i]*bv[j];
    }
    #pragma unroll
    for (int i=0;i<4;i++){
        float4 o0, o1;
        o0.x = acc[i][0] + sBu[tx*8+0];
        o0.y = acc[i][1] + sBu[tx*8+1];
        o0.z = acc[i][2] + sBu[tx*8+2];
        o0.w = acc[i][3] + sBu[tx*8+3];
        o1.x = acc[i][4] + sBu[tx*8+4];
        o1.y = acc[i][5] + sBu[tx*8+5];
        o1.z = acc[i][6] + sBu[tx*8+6];
        o1.w = acc[i][7] + sBu[tx*8+7];
        float* dst = out + (size_t)(m0+ty*4+i)*NDIM + n0 + tx*8;
        *(float4*)dst       = o0;
        *(float4*)(dst + 4) = o1;
    }
}

// ---------------- launch ----------------
extern "C" void kernel_launch(void* const* d_in, const int* in_sizes, int n_in,
                              void* d_out, int out_size)
{
    const float* input = (const float*)d_in[0];
    const float* subU  = (const float*)d_in[1];
    const void*  idx   = d_in[2];
    const float* Wd    = (const float*)d_in[3];
    const float* bd    = (const float*)d_in[4];
    const float* Wu    = (const float*)d_in[5];
    const float* bu    = (const float*)d_in[6];
    const float* Wa    = (const float*)d_in[7];
    const float* ba    = (const float*)d_in[8];
    const float* ga    = (const float*)d_in[9];
    const float* be    = (const float*)d_in[10];
    float* out = (float*)d_out;
    (void)in_sizes; (void)n_in; (void)out_size;

    cudaFuncSetAttribute(group_kernel, cudaFuncAttributeMaxDynamicSharedMemorySize, K3_SMEM);
    cudaFuncSetAttribute(up_kernel,    cudaFuncAttributeMaxDynamicSharedMemorySize, K4_SMEM);

    probe_idx_kernel<<<1, 128>>>((const unsigned int*)idx);
    convert_idx_kernel<<<(2*MT + 255)/256, 256>>>(idx);
    down_kernel<<<MT/64, 256>>>(input, Wd, bd);
    group_kernel<<<NB*NG, 256, K3_SMEM>>>(subU, Wa, ba, ga, be);
    combine_kernel<<<(MT*NR/4 + 255)/256, 256>>>();
    up_kernel<<<dim3(MT/64, 3), 256, K4_SMEM>>>(Wu, bu, out);
}

// round 9
// speedup vs baseline: 1.0002x; 1.0002x over previous
#include <cuda_runtime.h>
#include <cstdint>

#define NB 16
#define NN 8192
#define NDIM 384
#define NR 64
#define NG 128
#define NS 64
#define MT (NB*NN)   // 131072 rows

// ---------------- scratch (no allocations allowed) ----------------
__device__ __align__(256) float g_h[(size_t)MT*NR];   // 33.5 MB
__device__ __align__(256) float g_y[(size_t)MT*NR];   // 33.5 MB
__device__ __align__(256) int   g_idx[2*MT];          // normalized int32 indices
__device__ int g_is64;

__device__ __forceinline__ float silu_f(float x){ return x / (1.0f + __expf(-x)); }

__device__ __forceinline__ void fma4x4(float (&acc)[4][4], float4 a, float4 b){
    float av[4] = {a.x,a.y,a.z,a.w};
    float bv[4] = {b.x,b.y,b.z,b.w};
    #pragma unroll
    for (int i=0;i<4;i++)
        #pragma unroll
        for (int j=0;j<4;j++)
            acc[i][j] += av[i]*bv[j];
}

// ---------------- idx dtype probe + normalize ----------------
// Values are in [0, 8192). If the array is int64 (little-endian), every odd
// 32-bit word is 0. If int32, odd words are random nonzero indices
// (P[all 128 zero] ~ (1/8192)^128 ~ 0).
__global__ void probe_idx_kernel(const unsigned int* __restrict__ w){
    __shared__ int ok;
    if (threadIdx.x == 0) ok = 1;
    __syncthreads();
    if (w[2*threadIdx.x + 1] != 0u) ok = 0;   // benign race, all write 0
    __syncthreads();
    if (threadIdx.x == 0) g_is64 = ok;
}

__global__ void convert_idx_kernel(const void* __restrict__ p){
    int i = blockIdx.x*blockDim.x + threadIdx.x;
    if (i >= 2*MT) return;
    if (g_is64) g_idx[i] = (int)((const long long*)p)[i];
    else        g_idx[i] = ((const int*)p)[i];
}

// ---------------- K1: h = silu(X @ Wd^T + bd) ----------------
// C[131072,64] = A[131072,384] * Wd[64,384]^T. BM=64, BN=64, BK=32.
__global__ __launch_bounds__(256) void down_kernel(
    const float* __restrict__ A, const float* __restrict__ Wd,
    const float* __restrict__ bd)
{
    __shared__ float As[32][68];  // k-major: As[k][m]
    __shared__ float Bs[32][68];  // k-major: Bs[k][n] = Wd[n][k]
    const int tid = threadIdx.x;
    const int tx = tid & 15, ty = tid >> 4;
    const int m0 = blockIdx.x * 64;
    const int lr = tid >> 3;         // 0..31
    const int lk = (tid & 7) * 4;    // 0..28

    float acc[4][4] = {};
    for (int kk = 0; kk < NDIM; kk += 32){
        float4 a0 = *(const float4*)(A + (size_t)(m0+lr   )*NDIM + kk + lk);
        float4 a1 = *(const float4*)(A + (size_t)(m0+lr+32)*NDIM + kk + lk);
        float4 b0 = *(const float4*)(Wd + (size_t)(lr   )*NDIM + kk + lk);
        float4 b1 = *(const float4*)(Wd + (size_t)(lr+32)*NDIM + kk + lk);
        __syncthreads();
        As[lk+0][lr]=a0.x; As[lk+1][lr]=a0.y; As[lk+2][lr]=a0.z; As[lk+3][lr]=a0.w;
        As[lk+0][lr+32]=a1.x; As[lk+1][lr+32]=a1.y; As[lk+2][lr+32]=a1.z; As[lk+3][lr+32]=a1.w;
        Bs[lk+0][lr]=b0.x; Bs[lk+1][lr]=b0.y; Bs[lk+2][lr]=b0.z; Bs[lk+3][lr]=b0.w;
        Bs[lk+0][lr+32]=b1.x; Bs[lk+1][lr+32]=b1.y; Bs[lk+2][lr+32]=b1.z; Bs[lk+3][lr+32]=b1.w;
        __syncthreads();
        #pragma unroll
        for (int k = 0; k < 32; k++){
            float4 af = *(const float4*)&As[k][ty*4];
            float4 bf = *(const float4*)&Bs[k][tx*4];
            fma4x4(acc, af, bf);
        }
    }
    float4 bb = *(const float4*)(bd + tx*4);
    #pragma unroll
    for (int i=0;i<4;i++){
        float4 o;
        o.x = silu_f(acc[i][0] + bb.x);
        o.y = silu_f(acc[i][1] + bb.y);
        o.z = silu_f(acc[i][2] + bb.z);
        o.w = silu_f(acc[i][3] + bb.w);
        *(float4*)(g_h + (size_t)(m0+ty*4+i)*NR + tx*4) = o;
    }
}

// ---------------- K2: fused per-(b,g) branch (branch 1 only; branch 0 is dead)
//   X[t][r]  = h[b, idx0[b, g*64+t], r]          (gather fused into load)
//   F        = U^T @ X
//   F2       = F + silu(LN(F) @ Wa^T + ba)
//   Y        = U @ F2  -> g_y
#define K3_SMEM (5*64*68*4 + 3*64*4)
__global__ __launch_bounds__(256) void group_kernel(
    const float* __restrict__ subU, const float* __restrict__ Wa,
    const float* __restrict__ ba, const float* __restrict__ gamma,
    const float* __restrict__ beta)
{
    extern __shared__ float sm[];
    float* Ug  = sm;              // [64][68]  Ug[t][s]  = U[t][s] (as stored)
    float* Ut  = Ug  + 64*68;     // [64][68]  Ut[t][s]  = U[s][t] (transposed)
    float* Xs  = Ut  + 64*68;     // [64][68]  sub_x[t][r]; later LNT[k][s]
    float* Fs  = Xs  + 64*68;     // [64][68]  F[s][r]; later F2
    float* WaT = Fs  + 64*68;     // [64][68]  WaT[k][r] = Wa[r][k]
    float* sGa = WaT + 64*68;     // [64]
    float* sBe = sGa + 64;        // [64]
    float* sBa = sBe + 64;        // [64]

    const int tid = threadIdx.x;
    const int tx = tid & 15, ty = tid >> 4;
    const int bg = blockIdx.x;
    const int b = bg >> 7, g = bg & 127;
    const float* U = subU + ((size_t)(16 + b)*128 + g)*4096;  // sub_U[1][b][g]

    const int row = tid >> 2;        // 0..63
    const int c0  = (tid & 3) * 16;  // 0,16,32,48
    const int src = g_idx[b*NN + g*64 + row];                 // idx[0]
    const float* hsrc = g_h + ((size_t)b*NN + src)*NR;

    #pragma unroll
    for (int c = 0; c < 16; c += 4){
        float4 u = *(const float4*)(U + row*64 + c0 + c);
        *(float4*)&Ug[row*68 + c0 + c] = u;
        Ut[(c0+c+0)*68 + row] = u.x;
        Ut[(c0+c+1)*68 + row] = u.y;
        Ut[(c0+c+2)*68 + row] = u.z;
        Ut[(c0+c+3)*68 + row] = u.w;
        float4 w = *(const float4*)(Wa + row*64 + c0 + c);
        WaT[(c0+c+0)*68 + row] = w.x;
        WaT[(c0+c+1)*68 + row] = w.y;
        WaT[(c0+c+2)*68 + row] = w.z;
        WaT[(c0+c+3)*68 + row] = w.w;
        float4 x = *(const float4*)(hsrc + c0 + c);
        *(float4*)&Xs[row*68 + c0 + c] = x;
    }
    if (tid < 64){ sGa[tid]=gamma[tid]; sBe[tid]=beta[tid]; sBa[tid]=ba[tid]; }
    __syncthreads();

    // GEMM1: F[s][r] = sum_t U[t][s] * X[t][r]
    float accF[4][4] = {};
    #pragma unroll 8
    for (int t = 0; t < 64; t++){
        float4 af = *(const float4*)&Ug[t*68 + ty*4];
        float4 bf = *(const float4*)&Xs[t*68 + tx*4];
        fma4x4(accF, af, bf);
    }
    #pragma unroll
    for (int i=0;i<4;i++)
        *(float4*)&Fs[(ty*4+i)*68 + tx*4] =
            make_float4(accF[i][0],accF[i][1],accF[i][2],accF[i][3]);
    __syncthreads();

    // LayerNorm over r (64) for row s=row; ddof=0, eps=1e-5
    float ssum=0.f, ssq=0.f;
    #pragma unroll
    for (int c=0;c<16;c+=4){
        float4 f = *(const float4*)&Fs[row*68 + c0 + c];
        ssum += f.x+f.y+f.z+f.w;
        ssq  += f.x*f.x + f.y*f.y + f.z*f.z + f.w*f.w;
    }
    ssum += __shfl_xor_sync(0xffffffffu, ssum, 1);
    ssq  += __shfl_xor_sync(0xffffffffu, ssq , 1);
    ssum += __shfl_xor_sync(0xffffffffu, ssum, 2);
    ssq  += __shfl_xor_sync(0xffffffffu, ssq , 2);
    float mean = ssum * (1.0f/64.0f);
    float var  = ssq  * (1.0f/64.0f) - mean*mean;
    float rstd = rsqrtf(var + 1e-5f);
    // LNT[k][s] into Xs (transposed for GEMM2 A-side LDS.128)
    #pragma unroll
    for (int c=0;c<16;c+=4){
        float4 f = *(const float4*)&Fs[row*68 + c0 + c];
        Xs[(c0+c+0)*68 + row] = (f.x-mean)*rstd*sGa[c0+c+0] + sBe[c0+c+0];
        Xs[(c0+c+1)*68 + row] = (f.y-mean)*rstd*sGa[c0+c+1] + sBe[c0+c+1];
        Xs[(c0+c+2)*68 + row] = (f.z-mean)*rstd*sGa[c0+c+2] + sBe[c0+c+2];
        Xs[(c0+c+3)*68 + row] = (f.w-mean)*rstd*sGa[c0+c+3] + sBe[c0+c+3];
    }
    __syncthreads();

    // GEMM2: G[s][r] = sum_k LN(F)[s][k] * Wa[r][k];  F2 = F + silu(G + ba)
    float accG[4][4] = {};
    #pragma unroll 8
    for (int t = 0; t < 64; t++){
        float4 af = *(const float4*)&Xs[t*68 + ty*4];
        float4 bf = *(const float4*)&WaT[t*68 + tx*4];
        fma4x4(accG, af, bf);
    }
    #pragma unroll
    for (int i=0;i<4;i++){
        float4 o;
        o.x = accF[i][0] + silu_f(accG[i][0] + sBa[tx*4+0]);
        o.y = accF[i][1] + silu_f(accG[i][1] + sBa[tx*4+1]);
        o.z = accF[i][2] + silu_f(accG[i][2] + sBa[tx*4+2]);
        o.w = accF[i][3] + silu_f(accG[i][3] + sBa[tx*4+3]);
        *(float4*)&Fs[(ty*4+i)*68 + tx*4] = o;
    }
    __syncthreads();

    // GEMM3: Y[s][r] = sum_t U[s][t] * F2[t][r]
    float accY[4][4] = {};
    #pragma unroll 8
    for (int t = 0; t < 64; t++){
        float4 af = *(const float4*)&Ut[t*68 + ty*4];
        float4 bf = *(const float4*)&Fs[t*68 + tx*4];
        fma4x4(accY, af, bf);
    }
    float* yout = g_y + ((size_t)b*NN + g*64)*NR;
    #pragma unroll
    for (int i=0;i<4;i++)
        *(float4*)(yout + (size_t)(ty*4+i)*NR + tx*4) =
            make_float4(accY[i][0],accY[i][1],accY[i][2],accY[i][3]);
}

// ---------------- K3: h <- h + y + gather(y, idx[1])  (in-place, per-element RMW)
__global__ void combine_kernel(){
    int gid = blockIdx.x*blockDim.x + threadIdx.x;   // one float4 each
    if (gid >= MT*NR/4) return;
    int rowi = gid >> 4;          // row 0..131071
    int q    = (gid & 15) * 4;    // col offset
    int b = rowi >> 13, j = rowi & (NN-1);
    int src = g_idx[MT + b*NN + j];                   // idx[1]
    float4 yg = *(const float4*)(g_y + ((size_t)b*NN + src)*NR + q);
    float4 yd = *(const float4*)(g_y + (size_t)rowi*NR + q);
    float4 hh = *(const float4*)(g_h + (size_t)rowi*NR + q);
    hh.x += yg.x + yd.x;  hh.y += yg.y + yd.y;
    hh.z += yg.z + yd.z;  hh.w += yg.w + yd.w;
    *(float4*)(g_h + (size_t)rowi*NR + q) = hh;
}

// ---------------- K4: out = h @ Wu^T + bu ----------------
// out[131072,384] = h[131072,64] * Wu[384,64]^T. BM=64, BN=128, single K pass.
#define K4_SMEM (64*68*4 + 64*132*4 + 128*4)
__global__ __launch_bounds__(256) void up_kernel(
    const float* __restrict__ Wu, const float* __restrict__ bu,
    float* __restrict__ out)
{
    extern __shared__ float sm[];
    float* Hs  = sm;            // [64][68]   Hs[k][m]
    float* Ws  = Hs + 64*68;    // [64][132]  Ws[k][n] = Wu[n0+n][k]
    float* sBu = Ws + 64*132;   // [128]
    const int tid = threadIdx.x;
    const int tx = tid & 15, ty = tid >> 4;
    const int m0 = blockIdx.x * 64;
    const int n0 = blockIdx.y * 128;
    {
        int row = tid >> 2, c0 = (tid & 3)*16;
        const float* src = g_h + (size_t)(m0+row)*NR;
        #pragma unroll
        for (int c=0;c<16;c+=4){
            float4 v = *(const float4*)(src + c0 + c);
            Hs[(c0+c+0)*68 + row] = v.x;
            Hs[(c0+c+1)*68 + row] = v.y;
            Hs[(c0+c+2)*68 + row] = v.z;
            Hs[(c0+c+3)*68 + row] = v.w;
        }
        int nloc = tid >> 1, half = (tid & 1)*32;
        const float* wsrc = Wu + (size_t)(n0+nloc)*NR + half;
        #pragma unroll
        for (int c=0;c<32;c+=4){
            float4 w = *(const float4*)(wsrc + c);
            Ws[(half+c+0)*132 + nloc] = w.x;
            Ws[(half+c+1)*132 + nloc] = w.y;
            Ws[(half+c+2)*132 + nloc] = w.z;
            Ws[(half+c+3)*132 + nloc] = w.w;
        }
        if (tid < 128) sBu[tid] = bu[n0 + tid];
    }
    __syncthreads();

    float acc[4][8] = {};
    #pragma unroll 8
    for (int k=0;k<64;k++){
        float4 af = *(const float4*)&Hs[k*68 + ty*4];
        float4 b0 = *(const float4*)&Ws[k*132 + tx*8];
        float4 b1 = *(const float4*)&Ws[k*132 + tx*8 + 4];
        float av[4]={af.x,af.y,af.z,af.w};
        float bv[8]={b0.x,b0.y,b0.z,b0.w,b1.x,b1.y,b1.z,b1.w};
        #pragma unroll
        for (int i=0;i<4;i++)
            #pragma unroll
            for (int j=0;j<8;j++)
                acc[i][j] += av[i]*bv[j];
    }
    #pragma unroll
    for (int i=0;i<4;i++){
        float4 o0, o1;
        o0.x = acc[i][0] + sBu[tx*8+0];
        o0.y = acc[i][1] + sBu[tx*8+1];
        o0.z = acc[i][2] + sBu[tx*8+2];
        o0.w = acc[i][3] + sBu[tx*8+3];
        o1.x = acc[i][4] + sBu[tx*8+4];
        o1.y = acc[i][5] + sBu[tx*8+5];
        o1.z = acc[i][6] + sBu[tx*8+6];
        o1.w = acc[i][7] + sBu[tx*8+7];
        float* dst = out + (size_t)(m0+ty*4+i)*NDIM + n0 + tx*8;
        *(float4*)dst       = o0;
        *(float4*)(dst + 4) = o1;
    }
}

// ---------------- launch ----------------
extern "C" void kernel_launch(void* const* d_in, const int* in_sizes, int n_in,
                              void* d_out, int out_size)
{
    const float* input = (const float*)d_in[0];
    const float* subU  = (const float*)d_in[1];
    const void*  idx   = d_in[2];
    const float* Wd    = (const float*)d_in[3];
    const float* bd    = (const float*)d_in[4];
    const float* Wu    = (const float*)d_in[5];
    const float* bu    = (const float*)d_in[6];
    const float* Wa    = (const float*)d_in[7];
    const float* ba    = (const float*)d_in[8];
    const float* ga    = (const float*)d_in[9];
    const float* be    = (const float*)d_in[10];
    float* out = (float*)d_out;
    (void)in_sizes; (void)n_in; (void)out_size;

    cudaFuncSetAttribute(group_kernel, cudaFuncAttributeMaxDynamicSharedMemorySize, K3_SMEM);
    cudaFuncSetAttribute(up_kernel,    cudaFuncAttributeMaxDynamicSharedMemorySize, K4_SMEM);

    probe_idx_kernel<<<1, 128>>>((const unsigned int*)idx);
    convert_idx_kernel<<<(2*MT + 255)/256, 256>>>(idx);
    down_kernel<<<MT/64, 256>>>(input, Wd, bd);
    group_kernel<<<NB*NG, 256, K3_SMEM>>>(subU, Wa, ba, ga, be);
    combine_kernel<<<(MT*NR/4 + 255)/256, 256>>>();
    up_kernel<<<dim3(MT/64, 3), 256, K4_SMEM>>>(Wu, bu, out);
}

// round 10
// speedup vs baseline: 1.3357x; 1.3354x over previous
#include <cuda_runtime.h>
#include <cstdint>

#define NB 16
#define NN 8192
#define NDIM 384
#define NR 64
#define NG 128
#define MT (NB*NN)   // 131072 rows

// ---------------- scratch (no allocations allowed) ----------------
__device__ __align__(256) float g_h[(size_t)MT*NR];   // 33.5 MB
__device__ __align__(256) float g_y[(size_t)MT*NR];   // 33.5 MB
__device__ __align__(256) int   g_idx[2*MT];          // normalized int32 indices
__device__ int g_is64;

__device__ __forceinline__ float silu_f(float x){ return x / (1.0f + __expf(-x)); }

// ---------------- tf32 helpers ----------------
__device__ __forceinline__ uint32_t tf32_hi(float x){
    uint32_t r; asm("cvt.rna.tf32.f32 %0, %1;" : "=r"(r) : "f"(x)); return r;
}
__device__ __forceinline__ void tf32_split(float x, uint32_t& hi, uint32_t& lo){
    hi = tf32_hi(x);
    lo = tf32_hi(x - __uint_as_float(hi));
}
// D = A(16x8 tf32) * B(8x8 tf32) + D, fp32 accum
__device__ __forceinline__ void mma_tf32(float (&c)[4],
    uint32_t a0, uint32_t a1, uint32_t a2, uint32_t a3,
    uint32_t b0, uint32_t b1)
{
    asm volatile("mma.sync.aligned.m16n8k8.row.col.f32.tf32.tf32.f32 "
        "{%0,%1,%2,%3}, {%4,%5,%6,%7}, {%8,%9}, {%0,%1,%2,%3};\n"
        : "+f"(c[0]), "+f"(c[1]), "+f"(c[2]), "+f"(c[3])
        : "r"(a0), "r"(a1), "r"(a2), "r"(a3), "r"(b0), "r"(b1));
}
__device__ __forceinline__ void fma4x4(float (&acc)[4][4], float4 a, float4 b){
    float av[4] = {a.x,a.y,a.z,a.w};
    float bv[4] = {b.x,b.y,b.z,b.w};
    #pragma unroll
    for (int i=0;i<4;i++)
        #pragma unroll
        for (int j=0;j<4;j++)
            acc[i][j] += av[i]*bv[j];
}

// ---------------- idx dtype probe + normalize ----------------
__global__ void probe_idx_kernel(const unsigned int* __restrict__ w){
    __shared__ int ok;
    if (threadIdx.x == 0) ok = 1;
    __syncthreads();
    if (w[2*threadIdx.x + 1] != 0u) ok = 0;
    __syncthreads();
    if (threadIdx.x == 0) g_is64 = ok;
}
__global__ void convert_idx_kernel(const void* __restrict__ p){
    int i = blockIdx.x*blockDim.x + threadIdx.x;
    if (i >= 2*MT) return;
    if (g_is64) g_idx[i] = (int)((const long long*)p)[i];
    else        g_idx[i] = ((const int*)p)[i];
}

// ================= K1: h = silu(X @ Wd^T + bd), tf32 split-3 tensor cores ====
// C[131072,64] = A[131072,384] * Wd[64,384]^T
// BM=256, BN=64, BK=32. 8 warps, each 64m x 32n. m16n8k8 mma.
// Smem layout: row stride 40 floats (=8 mod 32 -> conflict-free frag LDS.64);
// within a row, chunk c (8 k-values) stored permuted {k0,k4,k1,k5,k2,k6,k3,k7}
// so one LDS.64 at [row][c*8 + t4*2] yields {A[row][k0+t4], A[row][k0+t4+4]}.
#define DK_SA 40
#define DK_SMEM ((256*DK_SA + 64*DK_SA)*4)   // 51200 B
__global__ __launch_bounds__(256) void down_kernel(
    const float* __restrict__ A, const float* __restrict__ Wd,
    const float* __restrict__ bd)
{
    extern __shared__ float sm[];
    float* As = sm;               // [256][40]
    float* Bs = sm + 256*DK_SA;   // [64][40]
    const int tid  = threadIdx.x;
    const int wid  = tid >> 5, lane = tid & 31;
    const int g    = lane >> 2, t4 = lane & 3;
    const int wm   = wid & 3,   wn = wid >> 2;   // 4 x 2 warp grid
    const int m0   = blockIdx.x * 256;

    const int lrow = tid >> 2, lc = tid & 3;     // load mapping (items of 8 floats)
    const float* Abase = A + (size_t)m0 * NDIM;

    float4 pa[4][2];
    float4 pb[2];

    // prefetch stage 0
    {
        #pragma unroll
        for (int i=0;i<4;i++){
            const float* p = Abase + (size_t)(lrow + i*64)*NDIM + lc*8;
            pa[i][0] = *(const float4*)p;
            pa[i][1] = *(const float4*)(p+4);
        }
        const float* p = Wd + (size_t)lrow*NDIM + lc*8;
        pb[0] = *(const float4*)p;
        pb[1] = *(const float4*)(p+4);
    }

    float acc[4][4][4] = {};   // [mt][nt][frag]

    for (int s = 0; s < 12; s++){
        __syncthreads();
        // store permuted
        #pragma unroll
        for (int i=0;i<4;i++){
            float* d = As + (lrow + i*64)*DK_SA + lc*8;
            *(float4*)(d)   = make_float4(pa[i][0].x, pa[i][1].x, pa[i][0].y, pa[i][1].y);
            *(float4*)(d+4) = make_float4(pa[i][0].z, pa[i][1].z, pa[i][0].w, pa[i][1].w);
        }
        {
            float* d = Bs + lrow*DK_SA + lc*8;
            *(float4*)(d)   = make_float4(pb[0].x, pb[1].x, pb[0].y, pb[1].y);
            *(float4*)(d+4) = make_float4(pb[0].z, pb[1].z, pb[0].w, pb[1].w);
        }
        __syncthreads();

        if (s < 11){   // prefetch next stage under the mma work
            #pragma unroll
            for (int i=0;i<4;i++){
                const float* p = Abase + (size_t)(lrow + i*64)*NDIM + (s+1)*32 + lc*8;
                pa[i][0] = *(const float4*)p;
                pa[i][1] = *(const float4*)(p+4);
            }
            const float* p = Wd + (size_t)lrow*NDIM + (s+1)*32 + lc*8;
            pb[0] = *(const float4*)p;
            pb[1] = *(const float4*)(p+4);
        }

        #pragma unroll 2
        for (int c8 = 0; c8 < 4; c8++){
            uint32_t ah[4][4], al[4][4];
            #pragma unroll
            for (int mt=0; mt<4; mt++){
                const float* base = As + (wm*64 + mt*16 + g)*DK_SA + c8*8 + t4*2;
                float2 r0 = *(const float2*)base;
                float2 r8 = *(const float2*)(base + 8*DK_SA);
                tf32_split(r0.x, ah[mt][0], al[mt][0]);   // (g,   k)
                tf32_split(r8.x, ah[mt][1], al[mt][1]);   // (g+8, k)
                tf32_split(r0.y, ah[mt][2], al[mt][2]);   // (g,   k+4)
                tf32_split(r8.y, ah[mt][3], al[mt][3]);   // (g+8, k+4)
            }
            uint32_t bh[4][2], bl[4][2];
            #pragma unroll
            for (int nt=0; nt<4; nt++){
                const float* base = Bs + (wn*32 + nt*8 + g)*DK_SA + c8*8 + t4*2;
                float2 b = *(const float2*)base;
                tf32_split(b.x, bh[nt][0], bl[nt][0]);
                tf32_split(b.y, bh[nt][1], bl[nt][1]);
            }
            #pragma unroll
            for (int mt=0; mt<4; mt++)
                #pragma unroll
                for (int nt=0; nt<4; nt++){
                    mma_tf32(acc[mt][nt], al[mt][0],al[mt][1],al[mt][2],al[mt][3], bh[nt][0],bh[nt][1]);
                    mma_tf32(acc[mt][nt], ah[mt][0],ah[mt][1],ah[mt][2],ah[mt][3], bl[nt][0],bl[nt][1]);
                    mma_tf32(acc[mt][nt], ah[mt][0],ah[mt][1],ah[mt][2],ah[mt][3], bh[nt][0],bh[nt][1]);
                }
        }
    }

    // epilogue: bias + silu -> g_h
    #pragma unroll
    for (int mt=0; mt<4; mt++){
        int row = m0 + wm*64 + mt*16 + g;
        #pragma unroll
        for (int nt=0; nt<4; nt++){
            int col = wn*32 + nt*8 + t4*2;
            float b0 = __ldg(bd+col), b1 = __ldg(bd+col+1);
            float* o = g_h + (size_t)row*NR + col;
            *(float2*)o =
                make_float2(silu_f(acc[mt][nt][0]+b0), silu_f(acc[mt][nt][1]+b1));
            *(float2*)(o + 8*NR) =
                make_float2(silu_f(acc[mt][nt][2]+b0), silu_f(acc[mt][nt][3]+b1));
        }
    }
}

// ================= K2: fused per-(b,g) branch (unchanged, FFMA) ==============
#define K3_SMEM (5*64*68*4 + 3*64*4)
__global__ __launch_bounds__(256) void group_kernel(
    const float* __restrict__ subU, const float* __restrict__ Wa,
    const float* __restrict__ ba, const float* __restrict__ gamma,
    const float* __restrict__ beta)
{
    extern __shared__ float sm[];
    float* Ug  = sm;
    float* Ut  = Ug  + 64*68;
    float* Xs  = Ut  + 64*68;
    float* Fs  = Xs  + 64*68;
    float* WaT = Fs  + 64*68;
    float* sGa = WaT + 64*68;
    float* sBe = sGa + 64;
    float* sBa = sBe + 64;

    const int tid = threadIdx.x;
    const int tx = tid & 15, ty = tid >> 4;
    const int bg = blockIdx.x;
    const int b = bg >> 7, g = bg & 127;
    const float* U = subU + ((size_t)(16 + b)*128 + g)*4096;  // sub_U[1][b][g]

    const int row = tid >> 2;
    const int c0  = (tid & 3) * 16;
    const int src = g_idx[b*NN + g*64 + row];                 // idx[0]
    const float* hsrc = g_h + ((size_t)b*NN + src)*NR;

    #pragma unroll
    for (int c = 0; c < 16; c += 4){
        float4 u = *(const float4*)(U + row*64 + c0 + c);
        *(float4*)&Ug[row*68 + c0 + c] = u;
        Ut[(c0+c+0)*68 + row] = u.x;
        Ut[(c0+c+1)*68 + row] = u.y;
        Ut[(c0+c+2)*68 + row] = u.z;
        Ut[(c0+c+3)*68 + row] = u.w;
        float4 w = *(const float4*)(Wa + row*64 + c0 + c);
        WaT[(c0+c+0)*68 + row] = w.x;
        WaT[(c0+c+1)*68 + row] = w.y;
        WaT[(c0+c+2)*68 + row] = w.z;
        WaT[(c0+c+3)*68 + row] = w.w;
        float4 x = *(const float4*)(hsrc + c0 + c);
        *(float4*)&Xs[row*68 + c0 + c] = x;
    }
    if (tid < 64){ sGa[tid]=gamma[tid]; sBe[tid]=beta[tid]; sBa[tid]=ba[tid]; }
    __syncthreads();

    float accF[4][4] = {};
    #pragma unroll 8
    for (int t = 0; t < 64; t++){
        float4 af = *(const float4*)&Ug[t*68 + ty*4];
        float4 bf = *(const float4*)&Xs[t*68 + tx*4];
        fma4x4(accF, af, bf);
    }
    #pragma unroll
    for (int i=0;i<4;i++)
        *(float4*)&Fs[(ty*4+i)*68 + tx*4] =
            make_float4(accF[i][0],accF[i][1],accF[i][2],accF[i][3]);
    __syncthreads();

    float ssum=0.f, ssq=0.f;
    #pragma unroll
    for (int c=0;c<16;c+=4){
        float4 f = *(const float4*)&Fs[row*68 + c0 + c];
        ssum += f.x+f.y+f.z+f.w;
        ssq  += f.x*f.x + f.y*f.y + f.z*f.z + f.w*f.w;
    }
    ssum += __shfl_xor_sync(0xffffffffu, ssum, 1);
    ssq  += __shfl_xor_sync(0xffffffffu, ssq , 1);
    ssum += __shfl_xor_sync(0xffffffffu, ssum, 2);
    ssq  += __shfl_xor_sync(0xffffffffu, ssq , 2);
    float mean = ssum * (1.0f/64.0f);
    float var  = ssq  * (1.0f/64.0f) - mean*mean;
    float rstd = rsqrtf(var + 1e-5f);
    #pragma unroll
    for (int c=0;c<16;c+=4){
        float4 f = *(const float4*)&Fs[row*68 + c0 + c];
        Xs[(c0+c+0)*68 + row] = (f.x-mean)*rstd*sGa[c0+c+0] + sBe[c0+c+0];
        Xs[(c0+c+1)*68 + row] = (f.y-mean)*rstd*sGa[c0+c+1] + sBe[c0+c+1];
        Xs[(c0+c+2)*68 + row] = (f.z-mean)*rstd*sGa[c0+c+2] + sBe[c0+c+2];
        Xs[(c0+c+3)*68 + row] = (f.w-mean)*rstd*sGa[c0+c+3] + sBe[c0+c+3];
    }
    __syncthreads();

    float accG[4][4] = {};
    #pragma unroll 8
    for (int t = 0; t < 64; t++){
        float4 af = *(const float4*)&Xs[t*68 + ty*4];
        float4 bf = *(const float4*)&WaT[t*68 + tx*4];
        fma4x4(accG, af, bf);
    }
    #pragma unroll
    for (int i=0;i<4;i++){
        float4 o;
        o.x = accF[i][0] + silu_f(accG[i][0] + sBa[tx*4+0]);
        o.y = accF[i][1] + silu_f(accG[i][1] + sBa[tx*4+1]);
        o.z = accF[i][2] + silu_f(accG[i][2] + sBa[tx*4+2]);
        o.w = accF[i][3] + silu_f(accG[i][3] + sBa[tx*4+3]);
        *(float4*)&Fs[(ty*4+i)*68 + tx*4] = o;
    }
    __syncthreads();

    float accY[4][4] = {};
    #pragma unroll 8
    for (int t = 0; t < 64; t++){
        float4 af = *(const float4*)&Ut[t*68 + ty*4];
        float4 bf = *(const float4*)&Fs[t*68 + tx*4];
        fma4x4(accY, af, bf);
    }
    float* yout = g_y + ((size_t)b*NN + g*64)*NR;
    #pragma unroll
    for (int i=0;i<4;i++)
        *(float4*)(yout + (size_t)(ty*4+i)*NR + tx*4) =
            make_float4(accY[i][0],accY[i][1],accY[i][2],accY[i][3]);
}

// ================= K3: out = (h + y + gather(y,idx1)) @ Wu^T + bu ===========
// tf32 split-3 tensor cores, combine fused into the A-tile load.
// BM=64, BN=384 (full N so A rows are read exactly once), K=64 single pass.
// 8 warps, each 64m x 48n (6 n-tiles).
#define UK_SA 72
#define UK_SMEM ((64*UK_SA + 384*UK_SA + 384)*4)   // 130560 B
__global__ __launch_bounds__(256) void up_kernel(
    const float* __restrict__ Wu, const float* __restrict__ bu,
    float* __restrict__ out)
{
    extern __shared__ float sm[];
    float* As  = sm;                 // [64][72]
    float* Bs  = sm + 64*UK_SA;      // [384][72]
    float* sBu = Bs + 384*UK_SA;     // [384]
    const int tid = threadIdx.x;
    const int wid = tid >> 5, lane = tid & 31;
    const int g = lane >> 2, t4 = lane & 3;
    const int m0 = blockIdx.x * 64;

    // A load: fused h + y + gather(y, idx1), permuted store. 512 items of 8 floats.
    #pragma unroll
    for (int i=0;i<2;i++){
        int item = tid + i*256;
        int row = item >> 3, cc = item & 7;
        int grow = m0 + row;
        int b = grow >> 13, j = grow & (NN-1);
        int src = g_idx[MT + (b<<13) + j];
        const float* hp = g_h + (size_t)grow*NR + cc*8;
        const float* yp = g_y + (size_t)grow*NR + cc*8;
        const float* gp = g_y + ((size_t)((b<<13) + src))*NR + cc*8;
        float4 h0 = *(const float4*)hp,     h1 = *(const float4*)(hp+4);
        float4 y0 = *(const float4*)yp,     y1 = *(const float4*)(yp+4);
        float4 q0 = *(const float4*)gp,     q1 = *(const float4*)(gp+4);
        float4 v0 = make_float4(h0.x+y0.x+q0.x, h0.y+y0.y+q0.y,
                                h0.z+y0.z+q0.z, h0.w+y0.w+q0.w);
        float4 v1 = make_float4(h1.x+y1.x+q1.x, h1.y+y1.y+q1.y,
                                h1.z+y1.z+q1.z, h1.w+y1.w+q1.w);
        float* d = As + row*UK_SA + cc*8;
        *(float4*)(d)   = make_float4(v0.x, v1.x, v0.y, v1.y);
        *(float4*)(d+4) = make_float4(v0.z, v1.z, v0.w, v1.w);
    }
    // B load: Wu[384][64], 3072 items / 256 threads = 12 iters
    #pragma unroll
    for (int i=0;i<12;i++){
        int item = tid + i*256;
        int n = item >> 3, cc = item & 7;
        const float* p = Wu + (size_t)n*NR + cc*8;
        float4 v0 = *(const float4*)p, v1 = *(const float4*)(p+4);
        float* d = Bs + n*UK_SA + cc*8;
        *(float4*)(d)   = make_float4(v0.x, v1.x, v0.y, v1.y);
        *(float4*)(d+4) = make_float4(v0.z, v1.z, v0.w, v1.w);
    }
    for (int i=tid; i<384; i+=256) sBu[i] = bu[i];
    __syncthreads();

    float acc[4][6][4] = {};   // [mt][nt][frag]
    #pragma unroll 2
    for (int c8 = 0; c8 < 8; c8++){
        uint32_t ah[4][4], al[4][4];
        #pragma unroll
        for (int mt=0; mt<4; mt++){
            const float* base = As + (mt*16 + g)*UK_SA + c8*8 + t4*2;
            float2 r0 = *(const float2*)base;
            float2 r8 = *(const float2*)(base + 8*UK_SA);
            tf32_split(r0.x, ah[mt][0], al[mt][0]);
            tf32_split(r8.x, ah[mt][1], al[mt][1]);
            tf32_split(r0.y, ah[mt][2], al[mt][2]);
            tf32_split(r8.y, ah[mt][3], al[mt][3]);
        }
        uint32_t bh[6][2], bl[6][2];
        #pragma unroll
        for (int nt=0; nt<6; nt++){
            const float* base = Bs + (wid*48 + nt*8 + g)*UK_SA + c8*8 + t4*2;
            float2 bv = *(const float2*)base;
            tf32_split(bv.x, bh[nt][0], bl[nt][0]);
            tf32_split(bv.y, bh[nt][1], bl[nt][1]);
        }
        #pragma unroll
        for (int mt=0; mt<4; mt++)
            #pragma unroll
            for (int nt=0; nt<6; nt++){
                mma_tf32(acc[mt][nt], al[mt][0],al[mt][1],al[mt][2],al[mt][3], bh[nt][0],bh[nt][1]);
                mma_tf32(acc[mt][nt], ah[mt][0],ah[mt][1],ah[mt][2],ah[mt][3], bl[nt][0],bl[nt][1]);
                mma_tf32(acc[mt][nt], ah[mt][0],ah[mt][1],ah[mt][2],ah[mt][3], bh[nt][0],bh[nt][1]);
            }
    }

    // epilogue: bias -> out
    #pragma unroll
    for (int mt=0; mt<4; mt++){
        int row = m0 + mt*16 + g;
        #pragma unroll
        for (int nt=0; nt<6; nt++){
            int col = wid*48 + nt*8 + t4*2;
            float b0 = sBu[col], b1 = sBu[col+1];
            float* o = out + (size_t)row*NDIM + col;
            *(float2*)o          = make_float2(acc[mt][nt][0]+b0, acc[mt][nt][1]+b1);
            *(float2*)(o + 8*NDIM) = make_float2(acc[mt][nt][2]+b0, acc[mt][nt][3]+b1);
        }
    }
}

// ---------------- launch ----------------
extern "C" void kernel_launch(void* const* d_in, const int* in_sizes, int n_in,
                              void* d_out, int out_size)
{
    const float* input = (const float*)d_in[0];
    const float* subU  = (const float*)d_in[1];
    const void*  idx   = d_in[2];
    const float* Wd    = (const float*)d_in[3];
    const float* bd    = (const float*)d_in[4];
    const float* Wu    = (const float*)d_in[5];
    const float* bu    = (const float*)d_in[6];
    const float* Wa    = (const float*)d_in[7];
    const float* ba    = (const float*)d_in[8];
    const float* ga    = (const float*)d_in[9];
    const float* be    = (const float*)d_in[10];
    float* out = (float*)d_out;
    (void)in_sizes; (void)n_in; (void)out_size;

    cudaFuncSetAttribute(down_kernel,  cudaFuncAttributeMaxDynamicSharedMemorySize, DK_SMEM);
    cudaFuncSetAttribute(group_kernel, cudaFuncAttributeMaxDynamicSharedMemorySize, K3_SMEM);
    cudaFuncSetAttribute(up_kernel,    cudaFuncAttributeMaxDynamicSharedMemorySize, UK_SMEM);

    probe_idx_kernel<<<1, 128>>>((const unsigned int*)idx);
    convert_idx_kernel<<<(2*MT + 255)/256, 256>>>(idx);
    down_kernel<<<MT/256, 256, DK_SMEM>>>(input, Wd, bd);
    group_kernel<<<NB*NG, 256, K3_SMEM>>>(subU, Wa, ba, ga, be);
    up_kernel<<<MT/64, 256, UK_SMEM>>>(Wu, bu, out);
}